// round 13
// baseline (speedup 1.0000x reference)
#include <cuda_runtime.h>
#include <cuda_bf16.h>
#include <cstdint>

// Problem constants
constexpr int Bc   = 2;
constexpr int Sc   = 2048;
constexpr int HIDc = 1024;
constexpr int NHc  = 16;
constexpr int HDc  = 64;           // HID / NH
constexpr int Mtot = Bc * Sc;      // 4096
constexpr size_t CHUNK = (size_t)Bc * Sc * HIDc;  // 4,194,304 floats
constexpr size_t WSZ   = (size_t)HIDc * HIDc;     // 1,048,576
constexpr int NROWS = Bc * NHc * Sc;              // 65536 softmax rows

__device__ float g_rowsum[NROWS];
// bf16 split-precision scratch
__device__ __nv_bfloat16 g_inh[3 * CHUNK];   // query,key,value inputs hi
__device__ __nv_bfloat16 g_inl[3 * CHUNK];   // lo
__device__ __nv_bfloat16 g_wh[4 * WSZ];      // Wq,Wk,Wv,Wo hi
__device__ __nv_bfloat16 g_wl[4 * WSZ];      // lo
__device__ __nv_bfloat16 g_qkvh[3 * CHUNK];  // projected Q,K,V hi
__device__ __nv_bfloat16 g_qkvl[3 * CHUNK];  // lo
__device__ __nv_bfloat16 g_ch[CHUNK];        // ctx hi
__device__ __nv_bfloat16 g_cl[CHUNK];        // ctx lo

__device__ __forceinline__ uint32_t smem_u32(const void* p) {
    uint32_t a;
    asm("{ .reg .u64 t; cvta.to.shared.u64 t, %1; cvt.u32.u64 %0, t; }"
        : "=r"(a) : "l"(p));
    return a;
}

#define LDSM4(r, addr) \
    asm volatile("ldmatrix.sync.aligned.m8n8.x4.shared.b16 {%0,%1,%2,%3}, [%4];" \
        : "=r"((r)[0]), "=r"((r)[1]), "=r"((r)[2]), "=r"((r)[3]) : "r"(addr))
#define LDSM2(r, addr) \
    asm volatile("ldmatrix.sync.aligned.m8n8.x2.shared.b16 {%0,%1}, [%2];" \
        : "=r"((r)[0]), "=r"((r)[1]) : "r"(addr))
#define LDSM2T(r, addr) \
    asm volatile("ldmatrix.sync.aligned.m8n8.x2.trans.shared.b16 {%0,%1}, [%2];" \
        : "=r"((r)[0]), "=r"((r)[1]) : "r"(addr))
#define MMA16816(c, a, b) \
    asm volatile("mma.sync.aligned.m16n8k16.row.col.f32.bf16.bf16.f32 " \
        "{%0,%1,%2,%3}, {%4,%5,%6,%7}, {%8,%9}, {%0,%1,%2,%3};" \
        : "+f"((c)[0]), "+f"((c)[1]), "+f"((c)[2]), "+f"((c)[3]) \
        : "r"((a)[0]), "r"((a)[1]), "r"((a)[2]), "r"((a)[3]), \
          "r"((b)[0]), "r"((b)[1]))
#define CPA(dst, src) \
    asm volatile("cp.async.cg.shared.global [%0], [%1], 16;" :: "r"(dst), "l"(src))
#define CPC() asm volatile("cp.async.commit_group;")
#define CPW(n) asm volatile("cp.async.wait_group %0;" :: "n"(n))

__device__ __forceinline__ void split2(float x, __nv_bfloat16& h, __nv_bfloat16& l) {
    h = __float2bfloat16(x);
    l = __float2bfloat16(x - __bfloat162float(h));
}

// ---------------------------------------------------------------------------
// Single merged conversion kernel (inputs + weights + rowsum zero).
// ---------------------------------------------------------------------------
constexpr int CVT_BLOCKS = (int)((3 * CHUNK + 4 * WSZ) / 1024);

__global__ __launch_bounds__(256) void convert_all(
    const float* __restrict__ q, const float* __restrict__ k,
    const float* __restrict__ v, const float* __restrict__ wq,
    const float* __restrict__ wk, const float* __restrict__ wv,
    const float* __restrict__ wo)
{
    const size_t gid = (size_t)blockIdx.x * 256 + threadIdx.x;
    if (gid < NROWS / 4)
        ((float4*)g_rowsum)[gid] = make_float4(0.f, 0.f, 0.f, 0.f);

    const size_t i = gid * 4;
    const float* src;
    __nv_bfloat16 *h, *l;
    size_t off;
    if (i < 3 * CHUNK) {
        const int s = (int)(i / CHUNK);
        off = i - (size_t)s * CHUNK;
        src = (s == 0) ? q : (s == 1) ? k : v;
        h = g_inh + (size_t)s * CHUNK; l = g_inl + (size_t)s * CHUNK;
    } else {
        const size_t i2 = i - 3 * CHUNK;
        const int s = (int)(i2 / WSZ);
        off = i2 - (size_t)s * WSZ;
        src = (s == 0) ? wq : (s == 1) ? wk : (s == 2) ? wv : wo;
        h = g_wh + (size_t)s * WSZ; l = g_wl + (size_t)s * WSZ;
    }

    float4 x = *(const float4*)(src + off);
    __nv_bfloat16 h0, h1, h2, h3, l0, l1, l2, l3;
    split2(x.x, h0, l0); split2(x.y, h1, l1);
    split2(x.z, h2, l2); split2(x.w, h3, l3);
    __nv_bfloat162 hp0(h0, h1), hp1(h2, h3), lp0(l0, l1), lp1(l2, l3);
    uint2 hv, lv;
    hv.x = *(uint32_t*)&hp0; hv.y = *(uint32_t*)&hp1;
    lv.x = *(uint32_t*)&lp0; lv.y = *(uint32_t*)&lp1;
    *(uint2*)(h + off) = hv;
    *(uint2*)(l + off) = lv;
}

// ---------------------------------------------------------------------------
// mma.sync bf16x3 GEMM with cp.async double buffering. (unchanged)
// ---------------------------------------------------------------------------
constexpr int GEMM_SMEM = 2 * 4 * 128 * 40 * 2;   // 81920

__global__ __launch_bounds__(256) void gemm_bf16x3(
    const float* __restrict__ b0, const float* __restrict__ b1,
    const float* __restrict__ b2, float* __restrict__ Cext, int qkv_mode)
{
    int a_sel, w_sel, osel;
    const float* bias;
    if (qkv_mode) {
        a_sel = w_sel = osel = blockIdx.z;
        bias = (blockIdx.z == 0) ? b0 : (blockIdx.z == 1) ? b1 : b2;
    } else {
        a_sel = 3; w_sel = 3; osel = -1; bias = b0;
    }
    const __nv_bfloat16* Ah = (a_sel < 3) ? g_inh + (size_t)a_sel * CHUNK : g_ch;
    const __nv_bfloat16* Al = (a_sel < 3) ? g_inl + (size_t)a_sel * CHUNK : g_cl;
    const __nv_bfloat16* Wh = g_wh + (size_t)w_sel * WSZ;
    const __nv_bfloat16* Wl = g_wl + (size_t)w_sel * WSZ;

    extern __shared__ __align__(128) char dsm[];
    constexpr int LDT = 40;
    constexpr int TILE = 128 * LDT * 2;
    constexpr int BUF  = 4 * TILE;
    const uint32_t sb = smem_u32(dsm);

    const int tid = threadIdx.x, wid = tid >> 5, lane = tid & 31;
    const int m0 = blockIdx.y * 128, n0 = blockIdx.x * 128;
    const int wm = wid >> 2, wn = wid & 3;

    float acc[4][4][4];
    #pragma unroll
    for (int i = 0; i < 4; i++)
        #pragma unroll
        for (int j = 0; j < 4; j++)
            #pragma unroll
            for (int t = 0; t < 4; t++) acc[i][j][t] = 0.0f;

    const int r0 = tid >> 2, c0v = (tid & 3) * 8;
    const int r1 = r0 + 64;
    const uint32_t sOff0 = r0 * (LDT * 2) + c0v * 2;
    const uint32_t sOff1 = r1 * (LDT * 2) + c0v * 2;

    const uint32_t aoff = ((lane & 15) * LDT + (lane >> 4) * 8) * 2;
    const uint32_t boff = ((lane & 7) * LDT + ((lane >> 3) & 1) * 8) * 2;

    auto issue = [&](int kc, int buf) {
        const int kb = kc * 32;
        const uint32_t base = sb + buf * BUF;
        const size_t gA0 = (size_t)(m0 + r0) * HIDc + kb + c0v;
        const size_t gA1 = (size_t)(m0 + r1) * HIDc + kb + c0v;
        const size_t gB0 = (size_t)(n0 + r0) * HIDc + kb + c0v;
        const size_t gB1 = (size_t)(n0 + r1) * HIDc + kb + c0v;
        CPA(base + 0 * TILE + sOff0, Ah + gA0);
        CPA(base + 0 * TILE + sOff1, Ah + gA1);
        CPA(base + 1 * TILE + sOff0, Al + gA0);
        CPA(base + 1 * TILE + sOff1, Al + gA1);
        CPA(base + 2 * TILE + sOff0, Wh + gB0);
        CPA(base + 2 * TILE + sOff1, Wh + gB1);
        CPA(base + 3 * TILE + sOff0, Wl + gB0);
        CPA(base + 3 * TILE + sOff1, Wl + gB1);
    };

    issue(0, 0); CPC();

    for (int kc = 0; kc < 32; kc++) {
        const int cur = kc & 1;
        if (kc < 31) { issue(kc + 1, cur ^ 1); CPC(); CPW(1); }
        else         { CPW(0); }
        __syncthreads();

        const uint32_t bA = sb + cur * BUF;
        #pragma unroll
        for (int ks = 0; ks < 32; ks += 16) {
            uint32_t af[4][4], bh[4][2], bl[4][2];
            #pragma unroll
            for (int i = 0; i < 4; i++)
                LDSM4(af[i], bA + 0 * TILE + ((wm * 64 + i * 16) * LDT + ks) * 2 + aoff);
            #pragma unroll
            for (int j = 0; j < 4; j++)
                LDSM2(bh[j], bA + 2 * TILE + ((wn * 32 + j * 8) * LDT + ks) * 2 + boff);
            #pragma unroll
            for (int i = 0; i < 4; i++)
                #pragma unroll
                for (int j = 0; j < 4; j++) MMA16816(acc[i][j], af[i], bh[j]);
            #pragma unroll
            for (int j = 0; j < 4; j++)
                LDSM2(bl[j], bA + 3 * TILE + ((wn * 32 + j * 8) * LDT + ks) * 2 + boff);
            #pragma unroll
            for (int i = 0; i < 4; i++)
                #pragma unroll
                for (int j = 0; j < 4; j++) MMA16816(acc[i][j], af[i], bl[j]);
            #pragma unroll
            for (int i = 0; i < 4; i++)
                LDSM4(af[i], bA + 1 * TILE + ((wm * 64 + i * 16) * LDT + ks) * 2 + aoff);
            #pragma unroll
            for (int i = 0; i < 4; i++)
                #pragma unroll
                for (int j = 0; j < 4; j++) MMA16816(acc[i][j], af[i], bh[j]);
        }
        __syncthreads();
    }

    const int er = lane >> 2, ec = (lane & 3) * 2;
    if (osel < 0) {
        #pragma unroll
        for (int j = 0; j < 4; j++) {
            const int n = n0 + wn * 32 + j * 8 + ec;
            const float bx = bias[n], by = bias[n + 1];
            #pragma unroll
            for (int i = 0; i < 4; i++) {
                const int m = m0 + wm * 64 + i * 16 + er;
                *(float2*)(Cext + (size_t)m * HIDc + n) =
                    make_float2(acc[i][j][0] + bx, acc[i][j][1] + by);
                *(float2*)(Cext + (size_t)(m + 8) * HIDc + n) =
                    make_float2(acc[i][j][2] + bx, acc[i][j][3] + by);
            }
        }
    } else {
        __nv_bfloat16* dh = g_qkvh + (size_t)osel * CHUNK;
        __nv_bfloat16* dl = g_qkvl + (size_t)osel * CHUNK;
        #pragma unroll
        for (int j = 0; j < 4; j++) {
            const int n = n0 + wn * 32 + j * 8 + ec;
            const float bx = bias[n], by = bias[n + 1];
            #pragma unroll
            for (int i = 0; i < 4; i++) {
                const int m = m0 + wm * 64 + i * 16 + er;
                #pragma unroll
                for (int half = 0; half < 2; half++) {
                    const float c0 = acc[i][j][half * 2 + 0] + bx;
                    const float c1 = acc[i][j][half * 2 + 1] + by;
                    __nv_bfloat16 h0, h1, l0, l1;
                    split2(c0, h0, l0); split2(c1, h1, l1);
                    __nv_bfloat162 hp(h0, h1), lp(l0, l1);
                    const size_t off = (size_t)(m + half * 8) * HIDc + n;
                    *(__nv_bfloat162*)(dh + off) = hp;
                    *(__nv_bfloat162*)(dl + off) = lp;
                }
            }
        }
    }
}

// ---------------------------------------------------------------------------
// Pass 1: rowsum only. QK bf16x3 MMA + exp (masked), atomicAdd per-row sums.
// NO e-store (the 537 MB write is gone). Grid (bh, q, k), bh fastest.
// ---------------------------------------------------------------------------
constexpr int SC_SMEM = 4 * 128 * 72 * 2;   // 73728

__global__ __launch_bounds__(256) void rowsum_mma_kernel(
    const float* __restrict__ sim, const int* __restrict__ amask,
    const float* __restrict__ beta_p)
{
    extern __shared__ __align__(128) char dsm[];
    constexpr int LDT = 72;
    constexpr int TILE = 128 * LDT * 2;
    const uint32_t sb = smem_u32(dsm);

    const int tid = threadIdx.x, wid = tid >> 5, lane = tid & 31;
    const int bh = blockIdx.x, b = bh >> 4, h = bh & 15;
    const int q0 = blockIdx.y * 128, k0 = blockIdx.z * 128;
    const int wm = wid >> 2, wn = wid & 3;

    {
        const __nv_bfloat16* srcs[4] = {g_qkvh, g_qkvl, g_qkvh + CHUNK, g_qkvl + CHUNK};
        const int rb[4] = {q0, q0, k0, k0};
        #pragma unroll
        for (int L = 0; L < 16; L++) {
            const int e = tid + L * 256;
            const int t = e >> 10, r = (e >> 3) & 127, c = e & 7;
            const size_t g = ((size_t)b * Sc + rb[t] + r) * HIDc + h * HDc + c * 8;
            CPA(sb + t * TILE + r * (LDT * 2) + c * 16, srcs[t] + g);
        }
        CPC(); CPW(0);
    }
    __syncthreads();

    float acc[4][4][4];
    #pragma unroll
    for (int i = 0; i < 4; i++)
        #pragma unroll
        for (int j = 0; j < 4; j++)
            #pragma unroll
            for (int t = 0; t < 4; t++) acc[i][j][t] = 0.0f;

    const uint32_t aoff = ((lane & 15) * LDT + (lane >> 4) * 8) * 2;
    const uint32_t boff = ((lane & 7) * LDT + ((lane >> 3) & 1) * 8) * 2;
    const uint32_t aQh = sb, aQl = sb + TILE, aKh = sb + 2 * TILE, aKl = sb + 3 * TILE;

    #pragma unroll
    for (int ks = 0; ks < 64; ks += 16) {
        uint32_t af[4][4], bhf[4][2], blf[4][2];
        #pragma unroll
        for (int i = 0; i < 4; i++)
            LDSM4(af[i], aQh + ((wm * 64 + i * 16) * LDT + ks) * 2 + aoff);
        #pragma unroll
        for (int j = 0; j < 4; j++)
            LDSM2(bhf[j], aKh + ((wn * 32 + j * 8) * LDT + ks) * 2 + boff);
        #pragma unroll
        for (int i = 0; i < 4; i++)
            #pragma unroll
            for (int j = 0; j < 4; j++) MMA16816(acc[i][j], af[i], bhf[j]);
        #pragma unroll
        for (int j = 0; j < 4; j++)
            LDSM2(blf[j], aKl + ((wn * 32 + j * 8) * LDT + ks) * 2 + boff);
        #pragma unroll
        for (int i = 0; i < 4; i++)
            #pragma unroll
            for (int j = 0; j < 4; j++) MMA16816(acc[i][j], af[i], blf[j]);
        #pragma unroll
        for (int i = 0; i < 4; i++)
            LDSM4(af[i], aQl + ((wm * 64 + i * 16) * LDT + ks) * 2 + aoff);
        #pragma unroll
        for (int i = 0; i < 4; i++)
            #pragma unroll
            for (int j = 0; j < 4; j++) MMA16816(acc[i][j], af[i], bhf[j]);
    }

    const float beta = *beta_p;
    const int er = lane >> 2, ec = (lane & 3) * 2;

    int2 mk[4];
    #pragma unroll
    for (int j = 0; j < 4; j++)
        mk[j] = *(const int2*)(amask + (size_t)b * Sc + k0 + wn * 32 + j * 8 + ec);

    #pragma unroll
    for (int i = 0; i < 4; i++) {
        #pragma unroll
        for (int half = 0; half < 2; half++) {
            const int q = q0 + wm * 64 + i * 16 + half * 8 + er;
            const float* simp = sim + ((size_t)b * Sc + q) * Sc + k0 + wn * 32;
            float rs = 0.0f;
            #pragma unroll
            for (int j = 0; j < 4; j++) {
                const float2 sv = *(const float2*)(simp + j * 8 + ec);
                const float a0 = acc[i][j][half * 2 + 0];
                const float a1 = acc[i][j][half * 2 + 1];
                const float e0 = (mk[j].x == 0) ? 0.0f : __expf(fmaf(beta, sv.x, a0 * 0.125f));
                const float e1 = (mk[j].y == 0) ? 0.0f : __expf(fmaf(beta, sv.y, a1 * 0.125f));
                rs += e0 + e1;
            }
            rs += __shfl_xor_sync(0xffffffffu, rs, 1);
            rs += __shfl_xor_sync(0xffffffffu, rs, 2);
            if ((lane & 3) == 0) atomicAdd(&g_rowsum[(size_t)bh * Sc + q], rs);
        }
    }
}

// ---------------------------------------------------------------------------
// Pass 2: fused weights + AV. Per block: 64-q strip; loop over 32 k-chunks
// of 64: recompute QK (bf16x3), exp, normalize with 1/rowsum, write FINAL w
// (only big store), split w to smem, AV MMA vs V chunk. K/V double-buffered.
// Dynamic smem (110848 B):
//   [0)      Qh,Ql : 2 x 64 x 72 halves (18432)
//   [18432)  K     : 2 bufs x (Kh+Kl)   (36864)
//   [55296)  V     : 2 bufs x (Vh+Vl)   (36864)
//   [92160)  Wh,Wl : 2 x 64 x 72 halves (18432)
//   [110592) inv   : 64 fp32            (256)
// ---------------------------------------------------------------------------
constexpr int WAV_SMEM = 110848;

__global__ __launch_bounds__(256) void wav_mma_kernel(
    const float* __restrict__ sim, const int* __restrict__ amask,
    const float* __restrict__ beta_p, float* __restrict__ attn)
{
    extern __shared__ __align__(128) char dsm[];
    constexpr int LDT = 72;
    constexpr uint32_t OF_QH = 0, OF_QL = 9216;
    constexpr uint32_t OF_K = 18432, KBUF = 18432;
    constexpr uint32_t OF_V = 55296, VBUF = 18432;
    constexpr uint32_t OF_WH = 92160, OF_WL = 101376, OF_INV = 110592;
    const uint32_t sb = smem_u32(dsm);
    float* s_inv = (float*)(dsm + OF_INV);

    const int tid = threadIdx.x, wid = tid >> 5, lane = tid & 31;
    const int bh = blockIdx.x, b = bh >> 4, h = bh & 15;   // bh fastest: sim in L2
    const int q0 = blockIdx.y * 64;
    const int wm = wid >> 2, wn = wid & 3;

    if (tid < 64) s_inv[tid] = 1.0f / g_rowsum[(size_t)bh * Sc + q0 + tid];

    const __nv_bfloat16* Qh = g_qkvh;
    const __nv_bfloat16* Ql = g_qkvl;
    const __nv_bfloat16* Kh = g_qkvh + CHUNK;
    const __nv_bfloat16* Kl = g_qkvl + CHUNK;
    const __nv_bfloat16* Vh = g_qkvh + 2 * CHUNK;
    const __nv_bfloat16* Vl = g_qkvl + 2 * CHUNK;

    const int r = tid >> 2, cq = (tid & 3) * 2;   // row 0..63, quads cq, cq+1

    // Q load folded into cp.async group 0
    {
        const size_t g = ((size_t)b * Sc + q0 + r) * HIDc + h * HDc + cq * 8;
        CPA(sb + OF_QH + r * 144 + cq * 16,      Qh + g);
        CPA(sb + OF_QH + r * 144 + cq * 16 + 16, Qh + g + 8);
        CPA(sb + OF_QL + r * 144 + cq * 16,      Ql + g);
        CPA(sb + OF_QL + r * 144 + cq * 16 + 16, Ql + g + 8);
    }
    auto issue = [&](int kc, int buf) {
        const size_t g = ((size_t)b * Sc + kc * 64 + r) * HIDc + h * HDc + cq * 8;
        const uint32_t kb_ = sb + OF_K + buf * KBUF;
        const uint32_t vb_ = sb + OF_V + buf * VBUF;
        CPA(kb_ + r * 144 + cq * 16,             Kh + g);
        CPA(kb_ + r * 144 + cq * 16 + 16,        Kh + g + 8);
        CPA(kb_ + 9216 + r * 144 + cq * 16,      Kl + g);
        CPA(kb_ + 9216 + r * 144 + cq * 16 + 16, Kl + g + 8);
        CPA(vb_ + r * 144 + cq * 16,             Vh + g);
        CPA(vb_ + r * 144 + cq * 16 + 16,        Vh + g + 8);
        CPA(vb_ + 9216 + r * 144 + cq * 16,      Vl + g);
        CPA(vb_ + 9216 + r * 144 + cq * 16 + 16, Vl + g + 8);
    };
    issue(0, 0); CPC();

    const uint32_t aoff = ((lane & 15) * LDT + (lane >> 4) * 8) * 2;
    const uint32_t boff = ((lane & 7) * LDT + ((lane >> 3) & 1) * 8) * 2;
    const float beta = *beta_p;
    const int er = lane >> 2, ec = (lane & 3) * 2;

    float accv[2][2][4];
    #pragma unroll
    for (int i = 0; i < 2; i++)
        #pragma unroll
        for (int j = 0; j < 2; j++)
            #pragma unroll
            for (int t = 0; t < 4; t++) accv[i][j][t] = 0.0f;

    for (int kc = 0; kc < 32; kc++) {
        const int cur = kc & 1;
        if (kc < 31) { issue(kc + 1, cur ^ 1); CPC(); CPW(1); }
        else         { CPW(0); }
        __syncthreads();

        // QK scores for this chunk (64q x 64k, reduce HD=64, 3 splits)
        float acs[2][2][4];
        #pragma unroll
        for (int i = 0; i < 2; i++)
            #pragma unroll
            for (int j = 0; j < 2; j++)
                #pragma unroll
                for (int t = 0; t < 4; t++) acs[i][j][t] = 0.0f;

        const uint32_t kcur = sb + OF_K + cur * KBUF;
        #pragma unroll
        for (int ks = 0; ks < 64; ks += 16) {
            uint32_t af[2][4], bhf[2][2], blf[2][2];
            #pragma unroll
            for (int i = 0; i < 2; i++)
                LDSM4(af[i], sb + OF_QH + ((wm * 32 + i * 16) * LDT + ks) * 2 + aoff);
            #pragma unroll
            for (int j = 0; j < 2; j++)
                LDSM2(bhf[j], kcur + ((wn * 16 + j * 8) * LDT + ks) * 2 + boff);
            #pragma unroll
            for (int i = 0; i < 2; i++)
                #pragma unroll
                for (int j = 0; j < 2; j++) MMA16816(acs[i][j], af[i], bhf[j]);
            #pragma unroll
            for (int j = 0; j < 2; j++)
                LDSM2(blf[j], kcur + 9216 + ((wn * 16 + j * 8) * LDT + ks) * 2 + boff);
            #pragma unroll
            for (int i = 0; i < 2; i++)
                #pragma unroll
                for (int j = 0; j < 2; j++) MMA16816(acs[i][j], af[i], blf[j]);
            #pragma unroll
            for (int i = 0; i < 2; i++)
                LDSM4(af[i], sb + OF_QL + ((wm * 32 + i * 16) * LDT + ks) * 2 + aoff);
            #pragma unroll
            for (int i = 0; i < 2; i++)
                #pragma unroll
                for (int j = 0; j < 2; j++) MMA16816(acs[i][j], af[i], bhf[j]);
        }

        // Epilogue: exp, normalize, write final w, split to smem.
        #pragma unroll
        for (int i = 0; i < 2; i++) {
            #pragma unroll
            for (int half = 0; half < 2; half++) {
                const int qrow = wm * 32 + i * 16 + half * 8 + er;
                const int q = q0 + qrow;
                const float iv = s_inv[qrow];
                #pragma unroll
                for (int j = 0; j < 2; j++) {
                    const int kk = kc * 64 + wn * 16 + j * 8 + ec;
                    const int2 mk = *(const int2*)(amask + (size_t)b * Sc + kk);
                    const float2 sv = *(const float2*)(sim + ((size_t)b * Sc + q) * Sc + kk);
                    const float a0 = acs[i][j][half * 2 + 0];
                    const float a1 = acs[i][j][half * 2 + 1];
                    const float e0 = (mk.x == 0) ? 0.0f : __expf(fmaf(beta, sv.x, a0 * 0.125f));
                    const float e1 = (mk.y == 0) ? 0.0f : __expf(fmaf(beta, sv.y, a1 * 0.125f));
                    const float w0 = e0 * iv, w1 = e1 * iv;
                    __stcs((float2*)(attn + ((size_t)bh * Sc + q) * Sc + kk),
                           make_float2(w0, w1));
                    __nv_bfloat16 h0, h1, l0, l1;
                    split2(w0, h0, l0); split2(w1, h1, l1);
                    const uint32_t wo = (qrow * LDT + wn * 16 + j * 8 + ec) * 2;
                    *(__nv_bfloat162*)(dsm + OF_WH + wo) = __nv_bfloat162(h0, h1);
                    *(__nv_bfloat162*)(dsm + OF_WL + wo) = __nv_bfloat162(l0, l1);
                }
            }
        }
        __syncthreads();

        // AV MMA: accv += w_split @ V chunk (reduce over 64 k)
        const uint32_t vcur = sb + OF_V + cur * VBUF;
        #pragma unroll
        for (int ks = 0; ks < 64; ks += 16) {
            uint32_t ah[2][4], bhf[2][2], blf[2][2];
            #pragma unroll
            for (int i = 0; i < 2; i++)
                LDSM4(ah[i], sb + OF_WH + ((wm * 32 + i * 16) * LDT + ks) * 2 + aoff);
            #pragma unroll
            for (int j = 0; j < 2; j++) {
                const uint32_t vbo = ((ks + (lane & 15)) * LDT + wn * 16 + j * 8) * 2;
                LDSM2T(bhf[j], vcur + vbo);
                LDSM2T(blf[j], vcur + 9216 + vbo);
            }
            #pragma unroll
            for (int i = 0; i < 2; i++)
                #pragma unroll
                for (int j = 0; j < 2; j++) MMA16816(accv[i][j], ah[i], bhf[j]);
            #pragma unroll
            for (int i = 0; i < 2; i++)
                #pragma unroll
                for (int j = 0; j < 2; j++) MMA16816(accv[i][j], ah[i], blf[j]);
            #pragma unroll
            for (int i = 0; i < 2; i++)
                LDSM4(ah[i], sb + OF_WL + ((wm * 32 + i * 16) * LDT + ks) * 2 + aoff);
            #pragma unroll
            for (int i = 0; i < 2; i++)
                #pragma unroll
                for (int j = 0; j < 2; j++) MMA16816(accv[i][j], ah[i], bhf[j]);
        }
        __syncthreads();
    }

    // ctx epilogue: split bf16 write. ctx[b, q, h*64 + d]
    #pragma unroll
    for (int j = 0; j < 2; j++) {
        const int d = h * HDc + wn * 16 + j * 8 + ec;
        #pragma unroll
        for (int i = 0; i < 2; i++) {
            const int q = q0 + wm * 32 + i * 16 + er;
            #pragma unroll
            for (int half = 0; half < 2; half++) {
                const float c0 = accv[i][j][half * 2 + 0];
                const float c1 = accv[i][j][half * 2 + 1];
                __nv_bfloat16 h0, h1, l0, l1;
                split2(c0, h0, l0); split2(c1, h1, l1);
                const size_t off = ((size_t)b * Sc + q + half * 8) * HIDc + d;
                *(__nv_bfloat162*)(g_ch + off) = __nv_bfloat162(h0, h1);
                *(__nv_bfloat162*)(g_cl + off) = __nv_bfloat162(l0, l1);
            }
        }
    }
}

// ---------------------------------------------------------------------------
// Launcher
// ---------------------------------------------------------------------------
extern "C" void kernel_launch(void* const* d_in, const int* in_sizes, int n_in,
                              void* d_out, int out_size)
{
    const float* query = (const float*)d_in[0];
    const float* key   = (const float*)d_in[1];
    const float* value = (const float*)d_in[2];
    const int*   amask = (const int*)  d_in[3];
    const float* sim   = (const float*)d_in[4];
    const float* Wq    = (const float*)d_in[5];
    const float* bq    = (const float*)d_in[6];
    const float* Wk    = (const float*)d_in[7];
    const float* bk    = (const float*)d_in[8];
    const float* Wv    = (const float*)d_in[9];
    const float* bv    = (const float*)d_in[10];
    const float* Wo    = (const float*)d_in[11];
    const float* bo    = (const float*)d_in[12];
    const float* beta  = (const float*)d_in[13];

    float* out  = (float*)d_out;
    float* attn = out + CHUNK;   // attention_weights region [B,NH,S,S]

    cudaFuncSetAttribute(gemm_bf16x3,
                         cudaFuncAttributeMaxDynamicSharedMemorySize, GEMM_SMEM);
    cudaFuncSetAttribute(rowsum_mma_kernel,
                         cudaFuncAttributeMaxDynamicSharedMemorySize, SC_SMEM);
    cudaFuncSetAttribute(wav_mma_kernel,
                         cudaFuncAttributeMaxDynamicSharedMemorySize, WAV_SMEM);

    // One conversion pass (inputs + weights + rowsum zero).
    convert_all<<<CVT_BLOCKS, 256>>>(query, key, value, Wq, Wk, Wv, Wo);

    // QKV projections in one launch -> split bf16 Q,K,V.
    dim3 gq(HIDc / 128, Mtot / 128, 3);       // (8, 32, 3)
    gemm_bf16x3<<<gq, 256, GEMM_SMEM>>>(bq, bk, bv, nullptr, 1);

    // Pass 1: rowsums (no e-store). bh fastest so sim tiles L2-shared.
    dim3 gs(Bc * NHc, Sc / 128, Sc / 128);    // (32, 16, 16)
    rowsum_mma_kernel<<<gs, 256, SC_SMEM>>>(sim, amask, beta);

    // Pass 2: recompute scores, write final weights, fused AV.
    dim3 ga(Bc * NHc, Sc / 64, 1);            // (32, 32)
    wav_mma_kernel<<<ga, 256, WAV_SMEM>>>(sim, amask, beta, attn);

    // Output projection (fp32 out).
    dim3 go(HIDc / 128, Mtot / 128, 1);       // (8, 32)
    gemm_bf16x3<<<go, 256, GEMM_SMEM>>>(bo, nullptr, nullptr, out, 0);
}

// round 14
// speedup vs baseline: 1.5623x; 1.5623x over previous
#include <cuda_runtime.h>
#include <cuda_bf16.h>
#include <cuda_fp16.h>
#include <cstdint>

// Problem constants
constexpr int Bc   = 2;
constexpr int Sc   = 2048;
constexpr int HIDc = 1024;
constexpr int NHc  = 16;
constexpr int HDc  = 64;           // HID / NH
constexpr int Mtot = Bc * Sc;      // 4096
constexpr size_t CHUNK = (size_t)Bc * Sc * HIDc;  // 4,194,304 floats
constexpr size_t WSZ   = (size_t)HIDc * HIDc;     // 1,048,576
constexpr int NROWS = Bc * NHc * Sc;              // 65536 softmax rows
constexpr size_t ESZ = (size_t)Bc * NHc * Sc * Sc; // 134,217,728

__device__ float g_rowsum[NROWS];
__device__ __half g_ebuf[ESZ];               // fp16 exp-scores intermediate
// bf16 split-precision scratch
__device__ __nv_bfloat16 g_inh[3 * CHUNK];   // query,key,value inputs hi
__device__ __nv_bfloat16 g_inl[3 * CHUNK];   // lo
__device__ __nv_bfloat16 g_wh[4 * WSZ];      // Wq,Wk,Wv,Wo hi
__device__ __nv_bfloat16 g_wl[4 * WSZ];      // lo
__device__ __nv_bfloat16 g_qkvh[3 * CHUNK];  // projected Q,K,V hi
__device__ __nv_bfloat16 g_qkvl[3 * CHUNK];  // lo
__device__ __nv_bfloat16 g_ch[CHUNK];        // ctx hi
__device__ __nv_bfloat16 g_cl[CHUNK];        // ctx lo

__device__ __forceinline__ uint32_t smem_u32(const void* p) {
    uint32_t a;
    asm("{ .reg .u64 t; cvta.to.shared.u64 t, %1; cvt.u32.u64 %0, t; }"
        : "=r"(a) : "l"(p));
    return a;
}

#define LDSM4(r, addr) \
    asm volatile("ldmatrix.sync.aligned.m8n8.x4.shared.b16 {%0,%1,%2,%3}, [%4];" \
        : "=r"((r)[0]), "=r"((r)[1]), "=r"((r)[2]), "=r"((r)[3]) : "r"(addr))
#define LDSM2(r, addr) \
    asm volatile("ldmatrix.sync.aligned.m8n8.x2.shared.b16 {%0,%1}, [%2];" \
        : "=r"((r)[0]), "=r"((r)[1]) : "r"(addr))
#define LDSM2T(r, addr) \
    asm volatile("ldmatrix.sync.aligned.m8n8.x2.trans.shared.b16 {%0,%1}, [%2];" \
        : "=r"((r)[0]), "=r"((r)[1]) : "r"(addr))
#define MMA16816(c, a, b) \
    asm volatile("mma.sync.aligned.m16n8k16.row.col.f32.bf16.bf16.f32 " \
        "{%0,%1,%2,%3}, {%4,%5,%6,%7}, {%8,%9}, {%0,%1,%2,%3};" \
        : "+f"((c)[0]), "+f"((c)[1]), "+f"((c)[2]), "+f"((c)[3]) \
        : "r"((a)[0]), "r"((a)[1]), "r"((a)[2]), "r"((a)[3]), \
          "r"((b)[0]), "r"((b)[1]))
#define CPA(dst, src) \
    asm volatile("cp.async.cg.shared.global [%0], [%1], 16;" :: "r"(dst), "l"(src))
#define CPC() asm volatile("cp.async.commit_group;")
#define CPW(n) asm volatile("cp.async.wait_group %0;" :: "n"(n))

__device__ __forceinline__ void split2(float x, __nv_bfloat16& h, __nv_bfloat16& l) {
    h = __float2bfloat16(x);
    l = __float2bfloat16(x - __bfloat162float(h));
}

// ---------------------------------------------------------------------------
// Single merged conversion kernel (inputs + weights + rowsum zero).
// ---------------------------------------------------------------------------
constexpr int CVT_BLOCKS = (int)((3 * CHUNK + 4 * WSZ) / 1024);

__global__ __launch_bounds__(256) void convert_all(
    const float* __restrict__ q, const float* __restrict__ k,
    const float* __restrict__ v, const float* __restrict__ wq,
    const float* __restrict__ wk, const float* __restrict__ wv,
    const float* __restrict__ wo)
{
    const size_t gid = (size_t)blockIdx.x * 256 + threadIdx.x;
    if (gid < NROWS / 4)
        ((float4*)g_rowsum)[gid] = make_float4(0.f, 0.f, 0.f, 0.f);

    const size_t i = gid * 4;
    const float* src;
    __nv_bfloat16 *h, *l;
    size_t off;
    if (i < 3 * CHUNK) {
        const int s = (int)(i / CHUNK);
        off = i - (size_t)s * CHUNK;
        src = (s == 0) ? q : (s == 1) ? k : v;
        h = g_inh + (size_t)s * CHUNK; l = g_inl + (size_t)s * CHUNK;
    } else {
        const size_t i2 = i - 3 * CHUNK;
        const int s = (int)(i2 / WSZ);
        off = i2 - (size_t)s * WSZ;
        src = (s == 0) ? wq : (s == 1) ? wk : (s == 2) ? wv : wo;
        h = g_wh + (size_t)s * WSZ; l = g_wl + (size_t)s * WSZ;
    }

    float4 x = *(const float4*)(src + off);
    __nv_bfloat16 h0, h1, h2, h3, l0, l1, l2, l3;
    split2(x.x, h0, l0); split2(x.y, h1, l1);
    split2(x.z, h2, l2); split2(x.w, h3, l3);
    __nv_bfloat162 hp0(h0, h1), hp1(h2, h3), lp0(l0, l1), lp1(l2, l3);
    uint2 hv, lv;
    hv.x = *(uint32_t*)&hp0; hv.y = *(uint32_t*)&hp1;
    lv.x = *(uint32_t*)&lp0; lv.y = *(uint32_t*)&lp1;
    *(uint2*)(h + off) = hv;
    *(uint2*)(l + off) = lv;
}

// ---------------------------------------------------------------------------
// mma.sync bf16x3 GEMM with cp.async double buffering. (unchanged from R12)
// ---------------------------------------------------------------------------
constexpr int GEMM_SMEM = 2 * 4 * 128 * 40 * 2;   // 81920

__global__ __launch_bounds__(256) void gemm_bf16x3(
    const float* __restrict__ b0, const float* __restrict__ b1,
    const float* __restrict__ b2, float* __restrict__ Cext, int qkv_mode)
{
    int a_sel, w_sel, osel;
    const float* bias;
    if (qkv_mode) {
        a_sel = w_sel = osel = blockIdx.z;
        bias = (blockIdx.z == 0) ? b0 : (blockIdx.z == 1) ? b1 : b2;
    } else {
        a_sel = 3; w_sel = 3; osel = -1; bias = b0;
    }
    const __nv_bfloat16* Ah = (a_sel < 3) ? g_inh + (size_t)a_sel * CHUNK : g_ch;
    const __nv_bfloat16* Al = (a_sel < 3) ? g_inl + (size_t)a_sel * CHUNK : g_cl;
    const __nv_bfloat16* Wh = g_wh + (size_t)w_sel * WSZ;
    const __nv_bfloat16* Wl = g_wl + (size_t)w_sel * WSZ;

    extern __shared__ __align__(128) char dsm[];
    constexpr int LDT = 40;
    constexpr int TILE = 128 * LDT * 2;
    constexpr int BUF  = 4 * TILE;
    const uint32_t sb = smem_u32(dsm);

    const int tid = threadIdx.x, wid = tid >> 5, lane = tid & 31;
    const int m0 = blockIdx.y * 128, n0 = blockIdx.x * 128;
    const int wm = wid >> 2, wn = wid & 3;

    float acc[4][4][4];
    #pragma unroll
    for (int i = 0; i < 4; i++)
        #pragma unroll
        for (int j = 0; j < 4; j++)
            #pragma unroll
            for (int t = 0; t < 4; t++) acc[i][j][t] = 0.0f;

    const int r0 = tid >> 2, c0v = (tid & 3) * 8;
    const int r1 = r0 + 64;
    const uint32_t sOff0 = r0 * (LDT * 2) + c0v * 2;
    const uint32_t sOff1 = r1 * (LDT * 2) + c0v * 2;

    const uint32_t aoff = ((lane & 15) * LDT + (lane >> 4) * 8) * 2;
    const uint32_t boff = ((lane & 7) * LDT + ((lane >> 3) & 1) * 8) * 2;

    auto issue = [&](int kc, int buf) {
        const int kb = kc * 32;
        const uint32_t base = sb + buf * BUF;
        const size_t gA0 = (size_t)(m0 + r0) * HIDc + kb + c0v;
        const size_t gA1 = (size_t)(m0 + r1) * HIDc + kb + c0v;
        const size_t gB0 = (size_t)(n0 + r0) * HIDc + kb + c0v;
        const size_t gB1 = (size_t)(n0 + r1) * HIDc + kb + c0v;
        CPA(base + 0 * TILE + sOff0, Ah + gA0);
        CPA(base + 0 * TILE + sOff1, Ah + gA1);
        CPA(base + 1 * TILE + sOff0, Al + gA0);
        CPA(base + 1 * TILE + sOff1, Al + gA1);
        CPA(base + 2 * TILE + sOff0, Wh + gB0);
        CPA(base + 2 * TILE + sOff1, Wh + gB1);
        CPA(base + 3 * TILE + sOff0, Wl + gB0);
        CPA(base + 3 * TILE + sOff1, Wl + gB1);
    };

    issue(0, 0); CPC();

    for (int kc = 0; kc < 32; kc++) {
        const int cur = kc & 1;
        if (kc < 31) { issue(kc + 1, cur ^ 1); CPC(); CPW(1); }
        else         { CPW(0); }
        __syncthreads();

        const uint32_t bA = sb + cur * BUF;
        #pragma unroll
        for (int ks = 0; ks < 32; ks += 16) {
            uint32_t af[4][4], bh[4][2], bl[4][2];
            #pragma unroll
            for (int i = 0; i < 4; i++)
                LDSM4(af[i], bA + 0 * TILE + ((wm * 64 + i * 16) * LDT + ks) * 2 + aoff);
            #pragma unroll
            for (int j = 0; j < 4; j++)
                LDSM2(bh[j], bA + 2 * TILE + ((wn * 32 + j * 8) * LDT + ks) * 2 + boff);
            #pragma unroll
            for (int i = 0; i < 4; i++)
                #pragma unroll
                for (int j = 0; j < 4; j++) MMA16816(acc[i][j], af[i], bh[j]);
            #pragma unroll
            for (int j = 0; j < 4; j++)
                LDSM2(bl[j], bA + 3 * TILE + ((wn * 32 + j * 8) * LDT + ks) * 2 + boff);
            #pragma unroll
            for (int i = 0; i < 4; i++)
                #pragma unroll
                for (int j = 0; j < 4; j++) MMA16816(acc[i][j], af[i], bl[j]);
            #pragma unroll
            for (int i = 0; i < 4; i++)
                LDSM4(af[i], bA + 1 * TILE + ((wm * 64 + i * 16) * LDT + ks) * 2 + aoff);
            #pragma unroll
            for (int i = 0; i < 4; i++)
                #pragma unroll
                for (int j = 0; j < 4; j++) MMA16816(acc[i][j], af[i], bh[j]);
        }
        __syncthreads();
    }

    const int er = lane >> 2, ec = (lane & 3) * 2;
    if (osel < 0) {
        #pragma unroll
        for (int j = 0; j < 4; j++) {
            const int n = n0 + wn * 32 + j * 8 + ec;
            const float bx = bias[n], by = bias[n + 1];
            #pragma unroll
            for (int i = 0; i < 4; i++) {
                const int m = m0 + wm * 64 + i * 16 + er;
                *(float2*)(Cext + (size_t)m * HIDc + n) =
                    make_float2(acc[i][j][0] + bx, acc[i][j][1] + by);
                *(float2*)(Cext + (size_t)(m + 8) * HIDc + n) =
                    make_float2(acc[i][j][2] + bx, acc[i][j][3] + by);
            }
        }
    } else {
        __nv_bfloat16* dh = g_qkvh + (size_t)osel * CHUNK;
        __nv_bfloat16* dl = g_qkvl + (size_t)osel * CHUNK;
        #pragma unroll
        for (int j = 0; j < 4; j++) {
            const int n = n0 + wn * 32 + j * 8 + ec;
            const float bx = bias[n], by = bias[n + 1];
            #pragma unroll
            for (int i = 0; i < 4; i++) {
                const int m = m0 + wm * 64 + i * 16 + er;
                #pragma unroll
                for (int half = 0; half < 2; half++) {
                    const float c0 = acc[i][j][half * 2 + 0] + bx;
                    const float c1 = acc[i][j][half * 2 + 1] + by;
                    __nv_bfloat16 h0, h1, l0, l1;
                    split2(c0, h0, l0); split2(c1, h1, l1);
                    __nv_bfloat162 hp(h0, h1), lp(l0, l1);
                    const size_t off = (size_t)(m + half * 8) * HIDc + n;
                    *(__nv_bfloat162*)(dh + off) = hp;
                    *(__nv_bfloat162*)(dl + off) = lp;
                }
            }
        }
    }
}

// ---------------------------------------------------------------------------
// Scores on tensor cores. Writes e as fp16 to g_ebuf (half the bytes) and
// accumulates fp32 rowsums. Grid: (bh, q, k) with bh fastest (sim L2-shared).
// ---------------------------------------------------------------------------
constexpr int SC_SMEM = 4 * 128 * 72 * 2;   // 73728

__global__ __launch_bounds__(256) void scores_mma_kernel(
    const float* __restrict__ sim, const int* __restrict__ amask,
    const float* __restrict__ beta_p)
{
    extern __shared__ __align__(128) char dsm[];
    constexpr int LDT = 72;
    constexpr int TILE = 128 * LDT * 2;
    const uint32_t sb = smem_u32(dsm);

    const int tid = threadIdx.x, wid = tid >> 5, lane = tid & 31;
    const int bh = blockIdx.x, b = bh >> 4, h = bh & 15;
    const int q0 = blockIdx.y * 128, k0 = blockIdx.z * 128;
    const int wm = wid >> 2, wn = wid & 3;

    {
        const __nv_bfloat16* srcs[4] = {g_qkvh, g_qkvl, g_qkvh + CHUNK, g_qkvl + CHUNK};
        const int rb[4] = {q0, q0, k0, k0};
        #pragma unroll
        for (int L = 0; L < 16; L++) {
            const int e = tid + L * 256;
            const int t = e >> 10, r = (e >> 3) & 127, c = e & 7;
            const size_t g = ((size_t)b * Sc + rb[t] + r) * HIDc + h * HDc + c * 8;
            CPA(sb + t * TILE + r * (LDT * 2) + c * 16, srcs[t] + g);
        }
        CPC(); CPW(0);
    }
    __syncthreads();

    float acc[4][4][4];
    #pragma unroll
    for (int i = 0; i < 4; i++)
        #pragma unroll
        for (int j = 0; j < 4; j++)
            #pragma unroll
            for (int t = 0; t < 4; t++) acc[i][j][t] = 0.0f;

    const uint32_t aoff = ((lane & 15) * LDT + (lane >> 4) * 8) * 2;
    const uint32_t boff = ((lane & 7) * LDT + ((lane >> 3) & 1) * 8) * 2;
    const uint32_t aQh = sb, aQl = sb + TILE, aKh = sb + 2 * TILE, aKl = sb + 3 * TILE;

    #pragma unroll
    for (int ks = 0; ks < 64; ks += 16) {
        uint32_t af[4][4], bhf[4][2], blf[4][2];
        #pragma unroll
        for (int i = 0; i < 4; i++)
            LDSM4(af[i], aQh + ((wm * 64 + i * 16) * LDT + ks) * 2 + aoff);
        #pragma unroll
        for (int j = 0; j < 4; j++)
            LDSM2(bhf[j], aKh + ((wn * 32 + j * 8) * LDT + ks) * 2 + boff);
        #pragma unroll
        for (int i = 0; i < 4; i++)
            #pragma unroll
            for (int j = 0; j < 4; j++) MMA16816(acc[i][j], af[i], bhf[j]);
        #pragma unroll
        for (int j = 0; j < 4; j++)
            LDSM2(blf[j], aKl + ((wn * 32 + j * 8) * LDT + ks) * 2 + boff);
        #pragma unroll
        for (int i = 0; i < 4; i++)
            #pragma unroll
            for (int j = 0; j < 4; j++) MMA16816(acc[i][j], af[i], blf[j]);
        #pragma unroll
        for (int i = 0; i < 4; i++)
            LDSM4(af[i], aQl + ((wm * 64 + i * 16) * LDT + ks) * 2 + aoff);
        #pragma unroll
        for (int i = 0; i < 4; i++)
            #pragma unroll
            for (int j = 0; j < 4; j++) MMA16816(acc[i][j], af[i], bhf[j]);
    }

    const float beta = *beta_p;
    const int er = lane >> 2, ec = (lane & 3) * 2;

    int2 mk[4];
    #pragma unroll
    for (int j = 0; j < 4; j++)
        mk[j] = *(const int2*)(amask + (size_t)b * Sc + k0 + wn * 32 + j * 8 + ec);

    #pragma unroll
    for (int i = 0; i < 4; i++) {
        #pragma unroll
        for (int half = 0; half < 2; half++) {
            const int q = q0 + wm * 64 + i * 16 + half * 8 + er;
            const float* simp = sim + ((size_t)b * Sc + q) * Sc + k0 + wn * 32;
            __half* ep = g_ebuf + ((size_t)bh * Sc + q) * Sc + k0 + wn * 32;
            float rs = 0.0f;
            #pragma unroll
            for (int j = 0; j < 4; j++) {
                const float2 sv = *(const float2*)(simp + j * 8 + ec);
                const float a0 = acc[i][j][half * 2 + 0];
                const float a1 = acc[i][j][half * 2 + 1];
                const float e0 = (mk[j].x == 0) ? 0.0f : __expf(fmaf(beta, sv.x, a0 * 0.125f));
                const float e1 = (mk[j].y == 0) ? 0.0f : __expf(fmaf(beta, sv.y, a1 * 0.125f));
                const __half2 hp = __floats2half2_rn(e0, e1);
                __stcs((__half2*)(ep + j * 8 + ec), hp);
                rs += e0 + e1;
            }
            rs += __shfl_xor_sync(0xffffffffu, rs, 1);
            rs += __shfl_xor_sync(0xffffffffu, rs, 2);
            if ((lane & 3) == 0) atomicAdd(&g_rowsum[(size_t)bh * Sc + q], rs);
        }
    }
}

// ---------------------------------------------------------------------------
// AV on tensor cores. BQ=64 tiles. Reads fp16 e (half traffic), normalizes
// to fp32 w (final attention_weights store), splits to bf16, MMA vs V.
// Dynamic smem (39168 B -> 5 CTA/SM):
//   [0)      stag : 2 x 64 rows x 80 B  (10240)   fp16 e tiles
//   [10240)  sWh  : 64 x 40 halves      (5120)
//   [15360)  sWl  : 64 x 40 halves      (5120)
//   [20480)  V    : 2 x (hi 4608 + lo 4608)  (18432)
//   [38912)  inv  : 64 fp32             (256)
// ---------------------------------------------------------------------------
constexpr int AV_SMEM = 39424;

__global__ __launch_bounds__(256) void av_mma_kernel(float* __restrict__ attn)
{
    extern __shared__ __align__(128) char dsm[];
    constexpr int LDA = 40;   // halves (80 B)
    constexpr int LDV = 72;   // halves (144 B)
    constexpr uint32_t STAGB = 5120;
    constexpr uint32_t OF_WH = 10240, OF_WL = 15360, OF_V = 20480, OF_INV = 38912;
    constexpr uint32_t VBUF = 9216, OF_VL = 4608;
    const uint32_t sb = smem_u32(dsm);
    float* s_inv = (float*)(dsm + OF_INV);

    const int tid = threadIdx.x, wid = tid >> 5, lane = tid & 31;
    const int bh = blockIdx.z, b = bh >> 4, h = bh & 15;
    const int q0 = blockIdx.x * 64;
    const int wm = wid >> 2, wn = wid & 3;

    if (tid < 64) s_inv[tid] = 1.0f / g_rowsum[(size_t)bh * Sc + q0 + tid];

    const __half* Ebase = g_ebuf + ((size_t)bh * Sc + q0) * Sc;
    float* Abase = attn + ((size_t)bh * Sc + q0) * Sc;
    const __nv_bfloat16* Vbh = g_qkvh + 2 * CHUNK + (size_t)b * Sc * HIDc + h * HDc;
    const __nv_bfloat16* Vbl = g_qkvl + 2 * CHUNK + (size_t)b * Sc * HIDc + h * HDc;

    const int er4 = tid >> 2, ec4 = tid & 3;   // e: 64 rows x 4 16B-quads
    const int vr = tid >> 3, vc = tid & 7;     // V: 32 rows x 8 16B-quads

    auto issue = [&](int kc, int buf) {
        const int kb = kc * 32;
        const uint32_t stb = sb + buf * STAGB;
        CPA(stb + er4 * 80 + ec4 * 16, Ebase + (size_t)er4 * Sc + kb + ec4 * 8);
        const size_t gv = (size_t)(kb + vr) * HIDc + vc * 8;
        CPA(sb + OF_V + buf * VBUF + vr * 144 + vc * 16, Vbh + gv);
        CPA(sb + OF_V + buf * VBUF + OF_VL + vr * 144 + vc * 16, Vbl + gv);
    };

    issue(0, 0); CPC();

    const uint32_t aoff = ((lane & 15) * LDA + (lane >> 4) * 8) * 2;

    float acc[2][2][4];
    #pragma unroll
    for (int i = 0; i < 2; i++)
        #pragma unroll
        for (int j = 0; j < 2; j++)
            #pragma unroll
            for (int t = 0; t < 4; t++) acc[i][j][t] = 0.0f;

    for (int kc = 0; kc < 64; kc++) {
        const int cur = kc & 1;
        if (kc < 63) { issue(kc + 1, cur ^ 1); CPC(); CPW(1); }
        else         { CPW(0); }
        __syncthreads();

        // Normalize: read 8 fp16 e's, w = e*inv -> stcs fp32 + split to smem.
        {
            const char* stg = dsm + cur * STAGB;
            const int ar = tid >> 2, ac = (tid & 3) * 8;   // 8 halves per thread
            const uint4 raw = *(const uint4*)(stg + ar * 80 + ac * 2);
            const float iv = s_inv[ar];
            float w[8];
            {
                const __half2* hp = (const __half2*)&raw;
                #pragma unroll
                for (int t = 0; t < 4; t++) {
                    const float2 ef = __half22float2(hp[t]);
                    w[t * 2 + 0] = ef.x * iv;
                    w[t * 2 + 1] = ef.y * iv;
                }
            }
            float* gp = Abase + (size_t)ar * Sc + kc * 32 + ac;
            __stcs((float4*)gp,       make_float4(w[0], w[1], w[2], w[3]));
            __stcs((float4*)(gp + 4), make_float4(w[4], w[5], w[6], w[7]));
            #pragma unroll
            for (int t = 0; t < 4; t++) {
                __nv_bfloat16 h0, h1, l0, l1;
                split2(w[t * 2 + 0], h0, l0); split2(w[t * 2 + 1], h1, l1);
                const uint32_t wo = (ar * LDA + ac + t * 2) * 2;
                *(__nv_bfloat162*)(dsm + OF_WH + wo) = __nv_bfloat162(h0, h1);
                *(__nv_bfloat162*)(dsm + OF_WL + wo) = __nv_bfloat162(l0, l1);
            }
        }
        __syncthreads();

        const uint32_t vb0 = sb + OF_V + cur * VBUF;
        #pragma unroll
        for (int ks = 0; ks < 32; ks += 16) {
            uint32_t ah[2][4], bhf[2][2], blf[2][2];
            #pragma unroll
            for (int i = 0; i < 2; i++)
                LDSM4(ah[i], sb + OF_WH + ((wm * 32 + i * 16) * LDA + ks) * 2 + aoff);
            #pragma unroll
            for (int j = 0; j < 2; j++) {
                const uint32_t vbo = ((ks + (lane & 15)) * LDV + wn * 16 + j * 8) * 2;
                LDSM2T(bhf[j], vb0 + vbo);
                LDSM2T(blf[j], vb0 + OF_VL + vbo);
            }
            #pragma unroll
            for (int i = 0; i < 2; i++)
                #pragma unroll
                for (int j = 0; j < 2; j++) MMA16816(acc[i][j], ah[i], bhf[j]);
            #pragma unroll
            for (int i = 0; i < 2; i++)
                #pragma unroll
                for (int j = 0; j < 2; j++) MMA16816(acc[i][j], ah[i], blf[j]);
            #pragma unroll
            for (int i = 0; i < 2; i++)
                LDSM4(ah[i], sb + OF_WL + ((wm * 32 + i * 16) * LDA + ks) * 2 + aoff);
            #pragma unroll
            for (int i = 0; i < 2; i++)
                #pragma unroll
                for (int j = 0; j < 2; j++) MMA16816(acc[i][j], ah[i], bhf[j]);
        }
        __syncthreads();
    }

    // Epilogue: ctx split bf16 write. ctx[b, q, h*64 + d]
    const int er = lane >> 2, ec = (lane & 3) * 2;
    #pragma unroll
    for (int j = 0; j < 2; j++) {
        const int d = h * HDc + wn * 16 + j * 8 + ec;
        #pragma unroll
        for (int i = 0; i < 2; i++) {
            const int q = q0 + wm * 32 + i * 16 + er;
            #pragma unroll
            for (int half = 0; half < 2; half++) {
                const float c0 = acc[i][j][half * 2 + 0];
                const float c1 = acc[i][j][half * 2 + 1];
                __nv_bfloat16 h0, h1, l0, l1;
                split2(c0, h0, l0); split2(c1, h1, l1);
                const size_t off = ((size_t)b * Sc + q + half * 8) * HIDc + d;
                *(__nv_bfloat162*)(g_ch + off) = __nv_bfloat162(h0, h1);
                *(__nv_bfloat162*)(g_cl + off) = __nv_bfloat162(l0, l1);
            }
        }
    }
}

// ---------------------------------------------------------------------------
// Launcher
// ---------------------------------------------------------------------------
extern "C" void kernel_launch(void* const* d_in, const int* in_sizes, int n_in,
                              void* d_out, int out_size)
{
    const float* query = (const float*)d_in[0];
    const float* key   = (const float*)d_in[1];
    const float* value = (const float*)d_in[2];
    const int*   amask = (const int*)  d_in[3];
    const float* sim   = (const float*)d_in[4];
    const float* Wq    = (const float*)d_in[5];
    const float* bq    = (const float*)d_in[6];
    const float* Wk    = (const float*)d_in[7];
    const float* bk    = (const float*)d_in[8];
    const float* Wv    = (const float*)d_in[9];
    const float* bv    = (const float*)d_in[10];
    const float* Wo    = (const float*)d_in[11];
    const float* bo    = (const float*)d_in[12];
    const float* beta  = (const float*)d_in[13];

    float* out  = (float*)d_out;
    float* attn = out + CHUNK;   // attention_weights region [B,NH,S,S]

    cudaFuncSetAttribute(gemm_bf16x3,
                         cudaFuncAttributeMaxDynamicSharedMemorySize, GEMM_SMEM);
    cudaFuncSetAttribute(scores_mma_kernel,
                         cudaFuncAttributeMaxDynamicSharedMemorySize, SC_SMEM);
    cudaFuncSetAttribute(av_mma_kernel,
                         cudaFuncAttributeMaxDynamicSharedMemorySize, AV_SMEM);

    // One conversion pass (inputs + weights + rowsum zero).
    convert_all<<<CVT_BLOCKS, 256>>>(query, key, value, Wq, Wk, Wv, Wo);

    // QKV projections in one launch -> split bf16 Q,K,V.
    dim3 gq(HIDc / 128, Mtot / 128, 3);       // (8, 32, 3)
    gemm_bf16x3<<<gq, 256, GEMM_SMEM>>>(bq, bk, bv, nullptr, 1);

    // Scores: fp16 e store + rowsums. bh fastest (sim tiles L2-shared).
    dim3 gs(Bc * NHc, Sc / 128, Sc / 128);    // (32, 16, 16)
    scores_mma_kernel<<<gs, 256, SC_SMEM>>>(sim, amask, beta);

    // Normalize + AV on tensor cores -> final weights + ctx split bf16.
    dim3 ga(Sc / 64, 1, Bc * NHc);            // (32, 1, 32)
    av_mma_kernel<<<ga, 256, AV_SMEM>>>(attn);

    // Output projection (fp32 out).
    dim3 go(HIDc / 128, Mtot / 128, 1);       // (8, 32)
    gemm_bf16x3<<<go, 256, GEMM_SMEM>>>(bo, nullptr, nullptr, out, 0);
}

// round 15
// speedup vs baseline: 1.6589x; 1.0618x over previous
#include <cuda_runtime.h>
#include <cuda_bf16.h>
#include <cuda_fp16.h>
#include <cstdint>

// Problem constants
constexpr int Bc   = 2;
constexpr int Sc   = 2048;
constexpr int HIDc = 1024;
constexpr int NHc  = 16;
constexpr int HDc  = 64;           // HID / NH
constexpr int Mtot = Bc * Sc;      // 4096
constexpr size_t CHUNK = (size_t)Bc * Sc * HIDc;  // 4,194,304 floats
constexpr size_t WSZ   = (size_t)HIDc * HIDc;     // 1,048,576
constexpr int NROWS = Bc * NHc * Sc;              // 65536 softmax rows
constexpr size_t ESZ = (size_t)Bc * NHc * Sc * Sc; // 134,217,728

__device__ float g_rowsum[NROWS];
__device__ __half g_ebuf[ESZ];               // fp16 exp-scores intermediate
__device__ __half g_vf16[CHUNK];             // projected V in fp16 (AV B operand)
// bf16 split-precision scratch
__device__ __nv_bfloat16 g_inh[3 * CHUNK];   // query,key,value inputs hi
__device__ __nv_bfloat16 g_inl[3 * CHUNK];   // lo
__device__ __nv_bfloat16 g_wh[4 * WSZ];      // Wq,Wk,Wv,Wo hi
__device__ __nv_bfloat16 g_wl[4 * WSZ];      // lo
__device__ __nv_bfloat16 g_qkvh[2 * CHUNK];  // projected Q,K hi
__device__ __nv_bfloat16 g_qkvl[2 * CHUNK];  // lo
__device__ __nv_bfloat16 g_ch[CHUNK];        // ctx hi
__device__ __nv_bfloat16 g_cl[CHUNK];        // ctx lo

__device__ __forceinline__ uint32_t smem_u32(const void* p) {
    uint32_t a;
    asm("{ .reg .u64 t; cvta.to.shared.u64 t, %1; cvt.u32.u64 %0, t; }"
        : "=r"(a) : "l"(p));
    return a;
}

#define LDSM4(r, addr) \
    asm volatile("ldmatrix.sync.aligned.m8n8.x4.shared.b16 {%0,%1,%2,%3}, [%4];" \
        : "=r"((r)[0]), "=r"((r)[1]), "=r"((r)[2]), "=r"((r)[3]) : "r"(addr))
#define LDSM2(r, addr) \
    asm volatile("ldmatrix.sync.aligned.m8n8.x2.shared.b16 {%0,%1}, [%2];" \
        : "=r"((r)[0]), "=r"((r)[1]) : "r"(addr))
#define LDSM2T(r, addr) \
    asm volatile("ldmatrix.sync.aligned.m8n8.x2.trans.shared.b16 {%0,%1}, [%2];" \
        : "=r"((r)[0]), "=r"((r)[1]) : "r"(addr))
#define MMA16816(c, a, b) \
    asm volatile("mma.sync.aligned.m16n8k16.row.col.f32.bf16.bf16.f32 " \
        "{%0,%1,%2,%3}, {%4,%5,%6,%7}, {%8,%9}, {%0,%1,%2,%3};" \
        : "+f"((c)[0]), "+f"((c)[1]), "+f"((c)[2]), "+f"((c)[3]) \
        : "r"((a)[0]), "r"((a)[1]), "r"((a)[2]), "r"((a)[3]), \
          "r"((b)[0]), "r"((b)[1]))
#define MMA16816F16(c, a, b) \
    asm volatile("mma.sync.aligned.m16n8k16.row.col.f32.f16.f16.f32 " \
        "{%0,%1,%2,%3}, {%4,%5,%6,%7}, {%8,%9}, {%0,%1,%2,%3};" \
        : "+f"((c)[0]), "+f"((c)[1]), "+f"((c)[2]), "+f"((c)[3]) \
        : "r"((a)[0]), "r"((a)[1]), "r"((a)[2]), "r"((a)[3]), \
          "r"((b)[0]), "r"((b)[1]))
#define CPA(dst, src) \
    asm volatile("cp.async.cg.shared.global [%0], [%1], 16;" :: "r"(dst), "l"(src))
#define CPC() asm volatile("cp.async.commit_group;")
#define CPW(n) asm volatile("cp.async.wait_group %0;" :: "n"(n))

__device__ __forceinline__ void split2(float x, __nv_bfloat16& h, __nv_bfloat16& l) {
    h = __float2bfloat16(x);
    l = __float2bfloat16(x - __bfloat162float(h));
}

// ---------------------------------------------------------------------------
// Single merged conversion kernel (inputs + weights + rowsum zero).
// ---------------------------------------------------------------------------
constexpr int CVT_BLOCKS = (int)((3 * CHUNK + 4 * WSZ) / 1024);

__global__ __launch_bounds__(256) void convert_all(
    const float* __restrict__ q, const float* __restrict__ k,
    const float* __restrict__ v, const float* __restrict__ wq,
    const float* __restrict__ wk, const float* __restrict__ wv,
    const float* __restrict__ wo)
{
    const size_t gid = (size_t)blockIdx.x * 256 + threadIdx.x;
    if (gid < NROWS / 4)
        ((float4*)g_rowsum)[gid] = make_float4(0.f, 0.f, 0.f, 0.f);

    const size_t i = gid * 4;
    const float* src;
    __nv_bfloat16 *h, *l;
    size_t off;
    if (i < 3 * CHUNK) {
        const int s = (int)(i / CHUNK);
        off = i - (size_t)s * CHUNK;
        src = (s == 0) ? q : (s == 1) ? k : v;
        h = g_inh + (size_t)s * CHUNK; l = g_inl + (size_t)s * CHUNK;
    } else {
        const size_t i2 = i - 3 * CHUNK;
        const int s = (int)(i2 / WSZ);
        off = i2 - (size_t)s * WSZ;
        src = (s == 0) ? wq : (s == 1) ? wk : (s == 2) ? wv : wo;
        h = g_wh + (size_t)s * WSZ; l = g_wl + (size_t)s * WSZ;
    }

    float4 x = *(const float4*)(src + off);
    __nv_bfloat16 h0, h1, h2, h3, l0, l1, l2, l3;
    split2(x.x, h0, l0); split2(x.y, h1, l1);
    split2(x.z, h2, l2); split2(x.w, h3, l3);
    __nv_bfloat162 hp0(h0, h1), hp1(h2, h3), lp0(l0, l1), lp1(l2, l3);
    uint2 hv, lv;
    hv.x = *(uint32_t*)&hp0; hv.y = *(uint32_t*)&hp1;
    lv.x = *(uint32_t*)&lp0; lv.y = *(uint32_t*)&lp1;
    *(uint2*)(h + off) = hv;
    *(uint2*)(l + off) = lv;
}

// ---------------------------------------------------------------------------
// mma.sync bf16x3 GEMM with cp.async double buffering.
// qkv_mode: z=0 -> Q (split bf16), z=1 -> K (split bf16), z=2 -> V (fp16).
// qkv_mode==0: ctx @ Wo -> fp32 out.
// ---------------------------------------------------------------------------
constexpr int GEMM_SMEM = 2 * 4 * 128 * 40 * 2;   // 81920

__global__ __launch_bounds__(256) void gemm_bf16x3(
    const float* __restrict__ b0, const float* __restrict__ b1,
    const float* __restrict__ b2, float* __restrict__ Cext, int qkv_mode)
{
    int a_sel, w_sel, osel;
    const float* bias;
    if (qkv_mode) {
        a_sel = w_sel = osel = blockIdx.z;
        bias = (blockIdx.z == 0) ? b0 : (blockIdx.z == 1) ? b1 : b2;
    } else {
        a_sel = 3; w_sel = 3; osel = -1; bias = b0;
    }
    const __nv_bfloat16* Ah = (a_sel < 3) ? g_inh + (size_t)a_sel * CHUNK : g_ch;
    const __nv_bfloat16* Al = (a_sel < 3) ? g_inl + (size_t)a_sel * CHUNK : g_cl;
    const __nv_bfloat16* Wh = g_wh + (size_t)w_sel * WSZ;
    const __nv_bfloat16* Wl = g_wl + (size_t)w_sel * WSZ;

    extern __shared__ __align__(128) char dsm[];
    constexpr int LDT = 40;
    constexpr int TILE = 128 * LDT * 2;
    constexpr int BUF  = 4 * TILE;
    const uint32_t sb = smem_u32(dsm);

    const int tid = threadIdx.x, wid = tid >> 5, lane = tid & 31;
    const int m0 = blockIdx.y * 128, n0 = blockIdx.x * 128;
    const int wm = wid >> 2, wn = wid & 3;

    float acc[4][4][4];
    #pragma unroll
    for (int i = 0; i < 4; i++)
        #pragma unroll
        for (int j = 0; j < 4; j++)
            #pragma unroll
            for (int t = 0; t < 4; t++) acc[i][j][t] = 0.0f;

    const int r0 = tid >> 2, c0v = (tid & 3) * 8;
    const int r1 = r0 + 64;
    const uint32_t sOff0 = r0 * (LDT * 2) + c0v * 2;
    const uint32_t sOff1 = r1 * (LDT * 2) + c0v * 2;

    const uint32_t aoff = ((lane & 15) * LDT + (lane >> 4) * 8) * 2;
    const uint32_t boff = ((lane & 7) * LDT + ((lane >> 3) & 1) * 8) * 2;

    auto issue = [&](int kc, int buf) {
        const int kb = kc * 32;
        const uint32_t base = sb + buf * BUF;
        const size_t gA0 = (size_t)(m0 + r0) * HIDc + kb + c0v;
        const size_t gA1 = (size_t)(m0 + r1) * HIDc + kb + c0v;
        const size_t gB0 = (size_t)(n0 + r0) * HIDc + kb + c0v;
        const size_t gB1 = (size_t)(n0 + r1) * HIDc + kb + c0v;
        CPA(base + 0 * TILE + sOff0, Ah + gA0);
        CPA(base + 0 * TILE + sOff1, Ah + gA1);
        CPA(base + 1 * TILE + sOff0, Al + gA0);
        CPA(base + 1 * TILE + sOff1, Al + gA1);
        CPA(base + 2 * TILE + sOff0, Wh + gB0);
        CPA(base + 2 * TILE + sOff1, Wh + gB1);
        CPA(base + 3 * TILE + sOff0, Wl + gB0);
        CPA(base + 3 * TILE + sOff1, Wl + gB1);
    };

    issue(0, 0); CPC();

    for (int kc = 0; kc < 32; kc++) {
        const int cur = kc & 1;
        if (kc < 31) { issue(kc + 1, cur ^ 1); CPC(); CPW(1); }
        else         { CPW(0); }
        __syncthreads();

        const uint32_t bA = sb + cur * BUF;
        #pragma unroll
        for (int ks = 0; ks < 32; ks += 16) {
            uint32_t af[4][4], bh[4][2], bl[4][2];
            #pragma unroll
            for (int i = 0; i < 4; i++)
                LDSM4(af[i], bA + 0 * TILE + ((wm * 64 + i * 16) * LDT + ks) * 2 + aoff);
            #pragma unroll
            for (int j = 0; j < 4; j++)
                LDSM2(bh[j], bA + 2 * TILE + ((wn * 32 + j * 8) * LDT + ks) * 2 + boff);
            #pragma unroll
            for (int i = 0; i < 4; i++)
                #pragma unroll
                for (int j = 0; j < 4; j++) MMA16816(acc[i][j], af[i], bh[j]);
            #pragma unroll
            for (int j = 0; j < 4; j++)
                LDSM2(bl[j], bA + 3 * TILE + ((wn * 32 + j * 8) * LDT + ks) * 2 + boff);
            #pragma unroll
            for (int i = 0; i < 4; i++)
                #pragma unroll
                for (int j = 0; j < 4; j++) MMA16816(acc[i][j], af[i], bl[j]);
            #pragma unroll
            for (int i = 0; i < 4; i++)
                LDSM4(af[i], bA + 1 * TILE + ((wm * 64 + i * 16) * LDT + ks) * 2 + aoff);
            #pragma unroll
            for (int i = 0; i < 4; i++)
                #pragma unroll
                for (int j = 0; j < 4; j++) MMA16816(acc[i][j], af[i], bh[j]);
        }
        __syncthreads();
    }

    const int er = lane >> 2, ec = (lane & 3) * 2;
    if (osel < 0) {
        #pragma unroll
        for (int j = 0; j < 4; j++) {
            const int n = n0 + wn * 32 + j * 8 + ec;
            const float bx = bias[n], by = bias[n + 1];
            #pragma unroll
            for (int i = 0; i < 4; i++) {
                const int m = m0 + wm * 64 + i * 16 + er;
                *(float2*)(Cext + (size_t)m * HIDc + n) =
                    make_float2(acc[i][j][0] + bx, acc[i][j][1] + by);
                *(float2*)(Cext + (size_t)(m + 8) * HIDc + n) =
                    make_float2(acc[i][j][2] + bx, acc[i][j][3] + by);
            }
        }
    } else if (osel == 2) {
        // V projection -> fp16 (single buffer)
        #pragma unroll
        for (int j = 0; j < 4; j++) {
            const int n = n0 + wn * 32 + j * 8 + ec;
            const float bx = bias[n], by = bias[n + 1];
            #pragma unroll
            for (int i = 0; i < 4; i++) {
                const int m = m0 + wm * 64 + i * 16 + er;
                #pragma unroll
                for (int half = 0; half < 2; half++) {
                    const float c0 = acc[i][j][half * 2 + 0] + bx;
                    const float c1 = acc[i][j][half * 2 + 1] + by;
                    const size_t off = (size_t)(m + half * 8) * HIDc + n;
                    *(__half2*)(g_vf16 + off) = __floats2half2_rn(c0, c1);
                }
            }
        }
    } else {
        __nv_bfloat16* dh = g_qkvh + (size_t)osel * CHUNK;
        __nv_bfloat16* dl = g_qkvl + (size_t)osel * CHUNK;
        #pragma unroll
        for (int j = 0; j < 4; j++) {
            const int n = n0 + wn * 32 + j * 8 + ec;
            const float bx = bias[n], by = bias[n + 1];
            #pragma unroll
            for (int i = 0; i < 4; i++) {
                const int m = m0 + wm * 64 + i * 16 + er;
                #pragma unroll
                for (int half = 0; half < 2; half++) {
                    const float c0 = acc[i][j][half * 2 + 0] + bx;
                    const float c1 = acc[i][j][half * 2 + 1] + by;
                    __nv_bfloat16 h0, h1, l0, l1;
                    split2(c0, h0, l0); split2(c1, h1, l1);
                    __nv_bfloat162 hp(h0, h1), lp(l0, l1);
                    const size_t off = (size_t)(m + half * 8) * HIDc + n;
                    *(__nv_bfloat162*)(dh + off) = hp;
                    *(__nv_bfloat162*)(dl + off) = lp;
                }
            }
        }
    }
}

// ---------------------------------------------------------------------------
// Scores on tensor cores (bf16x3, unchanged math). Writes e as fp16 to g_ebuf
// and accumulates fp32 rowsums. Grid: (bh, q, k), bh fastest (sim L2-shared).
// ---------------------------------------------------------------------------
constexpr int SC_SMEM = 4 * 128 * 72 * 2;   // 73728

__global__ __launch_bounds__(256) void scores_mma_kernel(
    const float* __restrict__ sim, const int* __restrict__ amask,
    const float* __restrict__ beta_p)
{
    extern __shared__ __align__(128) char dsm[];
    constexpr int LDT = 72;
    constexpr int TILE = 128 * LDT * 2;
    const uint32_t sb = smem_u32(dsm);

    const int tid = threadIdx.x, wid = tid >> 5, lane = tid & 31;
    const int bh = blockIdx.x, b = bh >> 4, h = bh & 15;
    const int q0 = blockIdx.y * 128, k0 = blockIdx.z * 128;
    const int wm = wid >> 2, wn = wid & 3;

    {
        const __nv_bfloat16* srcs[4] = {g_qkvh, g_qkvl, g_qkvh + CHUNK, g_qkvl + CHUNK};
        const int rb[4] = {q0, q0, k0, k0};
        #pragma unroll
        for (int L = 0; L < 16; L++) {
            const int e = tid + L * 256;
            const int t = e >> 10, r = (e >> 3) & 127, c = e & 7;
            const size_t g = ((size_t)b * Sc + rb[t] + r) * HIDc + h * HDc + c * 8;
            CPA(sb + t * TILE + r * (LDT * 2) + c * 16, srcs[t] + g);
        }
        CPC(); CPW(0);
    }
    __syncthreads();

    float acc[4][4][4];
    #pragma unroll
    for (int i = 0; i < 4; i++)
        #pragma unroll
        for (int j = 0; j < 4; j++)
            #pragma unroll
            for (int t = 0; t < 4; t++) acc[i][j][t] = 0.0f;

    const uint32_t aoff = ((lane & 15) * LDT + (lane >> 4) * 8) * 2;
    const uint32_t boff = ((lane & 7) * LDT + ((lane >> 3) & 1) * 8) * 2;
    const uint32_t aQh = sb, aQl = sb + TILE, aKh = sb + 2 * TILE, aKl = sb + 3 * TILE;

    #pragma unroll
    for (int ks = 0; ks < 64; ks += 16) {
        uint32_t af[4][4], bhf[4][2], blf[4][2];
        #pragma unroll
        for (int i = 0; i < 4; i++)
            LDSM4(af[i], aQh + ((wm * 64 + i * 16) * LDT + ks) * 2 + aoff);
        #pragma unroll
        for (int j = 0; j < 4; j++)
            LDSM2(bhf[j], aKh + ((wn * 32 + j * 8) * LDT + ks) * 2 + boff);
        #pragma unroll
        for (int i = 0; i < 4; i++)
            #pragma unroll
            for (int j = 0; j < 4; j++) MMA16816(acc[i][j], af[i], bhf[j]);
        #pragma unroll
        for (int j = 0; j < 4; j++)
            LDSM2(blf[j], aKl + ((wn * 32 + j * 8) * LDT + ks) * 2 + boff);
        #pragma unroll
        for (int i = 0; i < 4; i++)
            #pragma unroll
            for (int j = 0; j < 4; j++) MMA16816(acc[i][j], af[i], blf[j]);
        #pragma unroll
        for (int i = 0; i < 4; i++)
            LDSM4(af[i], aQl + ((wm * 64 + i * 16) * LDT + ks) * 2 + aoff);
        #pragma unroll
        for (int i = 0; i < 4; i++)
            #pragma unroll
            for (int j = 0; j < 4; j++) MMA16816(acc[i][j], af[i], bhf[j]);
    }

    const float beta = *beta_p;
    const int er = lane >> 2, ec = (lane & 3) * 2;

    int2 mk[4];
    #pragma unroll
    for (int j = 0; j < 4; j++)
        mk[j] = *(const int2*)(amask + (size_t)b * Sc + k0 + wn * 32 + j * 8 + ec);

    #pragma unroll
    for (int i = 0; i < 4; i++) {
        #pragma unroll
        for (int half = 0; half < 2; half++) {
            const int q = q0 + wm * 64 + i * 16 + half * 8 + er;
            const float* simp = sim + ((size_t)b * Sc + q) * Sc + k0 + wn * 32;
            __half* ep = g_ebuf + ((size_t)bh * Sc + q) * Sc + k0 + wn * 32;
            float rs = 0.0f;
            #pragma unroll
            for (int j = 0; j < 4; j++) {
                const float2 sv = *(const float2*)(simp + j * 8 + ec);
                const float a0 = acc[i][j][half * 2 + 0];
                const float a1 = acc[i][j][half * 2 + 1];
                const float e0 = (mk[j].x == 0) ? 0.0f : __expf(fmaf(beta, sv.x, a0 * 0.125f));
                const float e1 = (mk[j].y == 0) ? 0.0f : __expf(fmaf(beta, sv.y, a1 * 0.125f));
                const __half2 hp = __floats2half2_rn(e0, e1);
                __stcs((__half2*)(ep + j * 8 + ec), hp);
                rs += e0 + e1;
            }
            rs += __shfl_xor_sync(0xffffffffu, rs, 1);
            rs += __shfl_xor_sync(0xffffffffu, rs, 2);
            if ((lane & 3) == 0) atomicAdd(&g_rowsum[(size_t)bh * Sc + q], rs);
        }
    }
}

// ---------------------------------------------------------------------------
// AV on tensor cores: SINGLE fp16 MMA term (w_fp16 @ V_fp16, fp32 accum).
// Reads fp16 e, normalizes -> fp32 w store (final output) + fp16 w to smem.
// Dynamic smem (24832 B -> high occupancy):
//   [0)      stag : 2 x 64 rows x 80 B  (10240)   fp16 e tiles
//   [10240)  sW   : 64 x 40 halves      (5120)    fp16 w
//   [15360)  V    : 2 x 4608            (9216)    fp16 V
//   [24576)  inv  : 64 fp32             (256)
// ---------------------------------------------------------------------------
constexpr int AV_SMEM = 24832;

__global__ __launch_bounds__(256) void av_mma_kernel(float* __restrict__ attn)
{
    extern __shared__ __align__(128) char dsm[];
    constexpr int LDA = 40;   // halves (80 B)
    constexpr int LDV = 72;   // halves (144 B)
    constexpr uint32_t STAGB = 5120;
    constexpr uint32_t OF_W = 10240, OF_V = 15360, OF_INV = 24576;
    constexpr uint32_t VBUF = 4608;
    const uint32_t sb = smem_u32(dsm);
    float* s_inv = (float*)(dsm + OF_INV);

    const int tid = threadIdx.x, wid = tid >> 5, lane = tid & 31;
    const int bh = blockIdx.z, b = bh >> 4, h = bh & 15;
    const int q0 = blockIdx.x * 64;
    const int wm = wid >> 2, wn = wid & 3;

    if (tid < 64) s_inv[tid] = 1.0f / g_rowsum[(size_t)bh * Sc + q0 + tid];

    const __half* Ebase = g_ebuf + ((size_t)bh * Sc + q0) * Sc;
    float* Abase = attn + ((size_t)bh * Sc + q0) * Sc;
    const __half* Vf = g_vf16 + (size_t)b * Sc * HIDc + h * HDc;

    const int er4 = tid >> 2, ec4 = tid & 3;   // e: 64 rows x 4 16B-quads
    const int vr = tid >> 3, vc = tid & 7;     // V: 32 rows x 8 16B-quads

    auto issue = [&](int kc, int buf) {
        const int kb = kc * 32;
        CPA(sb + buf * STAGB + er4 * 80 + ec4 * 16,
            Ebase + (size_t)er4 * Sc + kb + ec4 * 8);
        CPA(sb + OF_V + buf * VBUF + vr * 144 + vc * 16,
            Vf + (size_t)(kb + vr) * HIDc + vc * 8);
    };

    issue(0, 0); CPC();

    const uint32_t aoff = ((lane & 15) * LDA + (lane >> 4) * 8) * 2;

    float acc[2][2][4];
    #pragma unroll
    for (int i = 0; i < 2; i++)
        #pragma unroll
        for (int j = 0; j < 2; j++)
            #pragma unroll
            for (int t = 0; t < 4; t++) acc[i][j][t] = 0.0f;

    for (int kc = 0; kc < 64; kc++) {
        const int cur = kc & 1;
        if (kc < 63) { issue(kc + 1, cur ^ 1); CPC(); CPW(1); }
        else         { CPW(0); }
        __syncthreads();

        // Normalize: w = e*inv -> fp32 streaming store + fp16 w to smem.
        {
            const char* stg = dsm + cur * STAGB;
            const int ar = tid >> 2, ac = (tid & 3) * 8;   // 8 halves / thread
            const uint4 raw = *(const uint4*)(stg + ar * 80 + ac * 2);
            const float iv = s_inv[ar];
            float w[8];
            {
                const __half2* hp = (const __half2*)&raw;
                #pragma unroll
                for (int t = 0; t < 4; t++) {
                    const float2 ef = __half22float2(hp[t]);
                    w[t * 2 + 0] = ef.x * iv;
                    w[t * 2 + 1] = ef.y * iv;
                }
            }
            float* gp = Abase + (size_t)ar * Sc + kc * 32 + ac;
            __stcs((float4*)gp,       make_float4(w[0], w[1], w[2], w[3]));
            __stcs((float4*)(gp + 4), make_float4(w[4], w[5], w[6], w[7]));
            #pragma unroll
            for (int t = 0; t < 4; t++) {
                const uint32_t wo = (ar * LDA + ac + t * 2) * 2;
                *(__half2*)(dsm + OF_W + wo) =
                    __floats2half2_rn(w[t * 2 + 0], w[t * 2 + 1]);
            }
        }
        __syncthreads();

        const uint32_t vb0 = sb + OF_V + cur * VBUF;
        #pragma unroll
        for (int ks = 0; ks < 32; ks += 16) {
            uint32_t ah[2][4], bf[2][2];
            #pragma unroll
            for (int i = 0; i < 2; i++)
                LDSM4(ah[i], sb + OF_W + ((wm * 32 + i * 16) * LDA + ks) * 2 + aoff);
            #pragma unroll
            for (int j = 0; j < 2; j++)
                LDSM2T(bf[j], vb0 + ((ks + (lane & 15)) * LDV + wn * 16 + j * 8) * 2);
            #pragma unroll
            for (int i = 0; i < 2; i++)
                #pragma unroll
                for (int j = 0; j < 2; j++) MMA16816F16(acc[i][j], ah[i], bf[j]);
        }
        __syncthreads();
    }

    // Epilogue: ctx split bf16 write. ctx[b, q, h*64 + d]
    const int er = lane >> 2, ec = (lane & 3) * 2;
    #pragma unroll
    for (int j = 0; j < 2; j++) {
        const int d = h * HDc + wn * 16 + j * 8 + ec;
        #pragma unroll
        for (int i = 0; i < 2; i++) {
            const int q = q0 + wm * 32 + i * 16 + er;
            #pragma unroll
            for (int half = 0; half < 2; half++) {
                const float c0 = acc[i][j][half * 2 + 0];
                const float c1 = acc[i][j][half * 2 + 1];
                __nv_bfloat16 h0, h1, l0, l1;
                split2(c0, h0, l0); split2(c1, h1, l1);
                const size_t off = ((size_t)b * Sc + q + half * 8) * HIDc + d;
                *(__nv_bfloat162*)(g_ch + off) = __nv_bfloat162(h0, h1);
                *(__nv_bfloat162*)(g_cl + off) = __nv_bfloat162(l0, l1);
            }
        }
    }
}

// ---------------------------------------------------------------------------
// Launcher
// ---------------------------------------------------------------------------
extern "C" void kernel_launch(void* const* d_in, const int* in_sizes, int n_in,
                              void* d_out, int out_size)
{
    const float* query = (const float*)d_in[0];
    const float* key   = (const float*)d_in[1];
    const float* value = (const float*)d_in[2];
    const int*   amask = (const int*)  d_in[3];
    const float* sim   = (const float*)d_in[4];
    const float* Wq    = (const float*)d_in[5];
    const float* bq    = (const float*)d_in[6];
    const float* Wk    = (const float*)d_in[7];
    const float* bk    = (const float*)d_in[8];
    const float* Wv    = (const float*)d_in[9];
    const float* bv    = (const float*)d_in[10];
    const float* Wo    = (const float*)d_in[11];
    const float* bo    = (const float*)d_in[12];
    const float* beta  = (const float*)d_in[13];

    float* out  = (float*)d_out;
    float* attn = out + CHUNK;   // attention_weights region [B,NH,S,S]

    cudaFuncSetAttribute(gemm_bf16x3,
                         cudaFuncAttributeMaxDynamicSharedMemorySize, GEMM_SMEM);
    cudaFuncSetAttribute(scores_mma_kernel,
                         cudaFuncAttributeMaxDynamicSharedMemorySize, SC_SMEM);
    cudaFuncSetAttribute(av_mma_kernel,
                         cudaFuncAttributeMaxDynamicSharedMemorySize, AV_SMEM);

    // One conversion pass (inputs + weights + rowsum zero).
    convert_all<<<CVT_BLOCKS, 256>>>(query, key, value, Wq, Wk, Wv, Wo);

    // QKV projections in one launch -> Q,K split bf16; V fp16.
    dim3 gq(HIDc / 128, Mtot / 128, 3);       // (8, 32, 3)
    gemm_bf16x3<<<gq, 256, GEMM_SMEM>>>(bq, bk, bv, nullptr, 1);

    // Scores: fp16 e store + rowsums. bh fastest (sim tiles L2-shared).
    dim3 gs(Bc * NHc, Sc / 128, Sc / 128);    // (32, 16, 16)
    scores_mma_kernel<<<gs, 256, SC_SMEM>>>(sim, amask, beta);

    // Normalize + AV (single fp16 MMA) -> final weights + ctx split bf16.
    dim3 ga(Sc / 64, 1, Bc * NHc);            // (32, 1, 32)
    av_mma_kernel<<<ga, 256, AV_SMEM>>>(attn);

    // Output projection (fp32 out).
    dim3 go(HIDc / 128, Mtot / 128, 1);       // (8, 32)
    gemm_bf16x3<<<go, 256, GEMM_SMEM>>>(bo, nullptr, nullptr, out, 0);
}